// round 1
// baseline (speedup 1.0000x reference)
#include <cuda_runtime.h>
#include <cstdint>

#define NN 100000
#define EE 1600000
#define INC 128
#define H1C 64      // HEADS*HID
#define HEADS 8
#define OUTC 40

// ---------------- scratch (device globals; no cudaMalloc allowed) -------------
__device__ float g_h1[NN * H1C];       // layer1 projected features
__device__ float g_as1[NN * HEADS];    // a_src per node per head
__device__ float g_ad1[NN * HEADS];
__device__ float g_acc1[NN * H1C];     // numerator accumulator (init w/ self loop)
__device__ float g_den1[NN * HEADS];   // denominator
__device__ float g_z[NN * H1C];        // elu(layer1 out)
__device__ float g_h2[NN * OUTC];
__device__ float g_as2[NN];
__device__ float g_ad2[NN];
__device__ float g_acc2[NN * OUTC];
__device__ float g_den2[NN];

__device__ __forceinline__ void red2(float* addr, float x, float y) {
    asm volatile("red.global.add.v2.f32 [%0], {%1, %2};"
                 :: "l"(addr), "f"(x), "f"(y) : "memory");
}

__device__ __forceinline__ float leaky(float t) {
    return t > 0.f ? t : 0.2f * t;
}

// ---------------- K1: GEMM1 + attention halves + self-loop init --------------
// block = 256 threads = 16 nodes x 16 col-groups(4 cols each)
__global__ __launch_bounds__(256) void k_gemm1(
    const float* __restrict__ x, const float* __restrict__ W1,
    const float* __restrict__ att_s, const float* __restrict__ att_d)
{
    __shared__ float sx[16 * 132];   // padded pitch 132 (33 float4)
    __shared__ float swv[16][8];
    int tid = threadIdx.x;
    int node0 = blockIdx.x * 16;

    // stage 16 x-rows (2048 floats = 512 float4), padded pitch
    const float4* x4 = (const float4*)(x + (size_t)node0 * INC);
    float4* sx4 = (float4*)sx;
    {
        int i0 = tid, i1 = tid + 256;
        sx4[(i0 >> 5) * 33 + (i0 & 31)] = x4[i0];
        sx4[(i1 >> 5) * 33 + (i1 & 31)] = x4[i1];
    }
    __syncthreads();

    int ln = tid >> 4;        // local node 0..15
    int cg = tid & 15;        // col group: cols 4cg..4cg+3
    const float* xr = sx + ln * 132;
    const float4* W4 = (const float4*)W1;   // [128][16] float4
    float4 acc = make_float4(0.f, 0.f, 0.f, 0.f);
#pragma unroll 8
    for (int k = 0; k < INC; k++) {
        float xv = xr[k];
        float4 w = W4[k * 16 + cg];
        acc.x += xv * w.x; acc.y += xv * w.y;
        acc.z += xv * w.z; acc.w += xv * w.w;
    }
    // attention partials: head = cg>>1
    float4 as = *(const float4*)(att_s + cg * 4);
    float4 ad = *(const float4*)(att_d + cg * 4);
    float ps = acc.x * as.x + acc.y * as.y + acc.z * as.z + acc.w * as.w;
    float pd = acc.x * ad.x + acc.y * ad.y + acc.z * ad.z + acc.w * ad.w;
    ps += __shfl_xor_sync(0xffffffffu, ps, 1);
    pd += __shfl_xor_sync(0xffffffffu, pd, 1);

    int n = node0 + ln;
    if ((cg & 1) == 0) {
        int h = cg >> 1;
        g_as1[n * HEADS + h] = ps;
        g_ad1[n * HEADS + h] = pd;
        float w = __expf(leaky(ps + pd));     // self-loop weight (ew=1)
        g_den1[n * HEADS + h] = w;
        swv[ln][h] = w;
    }
    __syncthreads();
    float wself = swv[ln][cg >> 1];
    *(float4*)(g_h1 + (size_t)n * H1C + cg * 4) = acc;
    float4 ai = make_float4(wself * acc.x, wself * acc.y, wself * acc.z, wself * acc.w);
    *(float4*)(g_acc1 + (size_t)n * H1C + cg * 4) = ai;
}

// ---------------- K2: layer-1 edge pass (warp per edge) ----------------------
__global__ __launch_bounds__(256) void k_edge1(
    const int* __restrict__ ei, const float* __restrict__ ew, int e)
{
    int gw = (blockIdx.x * blockDim.x + threadIdx.x) >> 5;
    if (gw >= e) return;
    int lane = threadIdx.x & 31;
    int s = __ldg(&ei[gw]);
    int d = __ldg(&ei[e + gw]);
    float wgt = __ldg(&ew[gw]);

    float w = 0.f;
    if (lane < 8) {
        float t = g_as1[s * HEADS + lane] + g_ad1[d * HEADS + lane];
        w = __expf(leaky(t));
        atomicAdd(&g_den1[d * HEADS + lane], w);
    }
    // channels (2*lane, 2*lane+1) -> head = lane>>2
    float wh = __shfl_sync(0xffffffffu, w, lane >> 2) * wgt;
    float2 hv = *(const float2*)(g_h1 + (size_t)s * H1C + lane * 2);
    red2(g_acc1 + (size_t)d * H1C + lane * 2, wh * hv.x, wh * hv.y);
}

// ---------------- K3: finalize layer-1 -> z = elu(acc/den + bias1) -----------
__global__ __launch_bounds__(256) void k_zfin(const float* __restrict__ b1, int n)
{
    int i = blockIdx.x * blockDim.x + threadIdx.x;
    if (i >= n * H1C) return;
    int node = i >> 6;
    int j = i & 63;
    float v = g_acc1[i] / (g_den1[node * HEADS + (j >> 3)] + 1e-16f) + b1[j];
    g_z[i] = v > 0.f ? v : expm1f(v);
}

// ---------------- K4: GEMM2 + attention + self-loop init ---------------------
// block = 256 = 32 nodes x 8 col-groups(5 cols each)
__global__ __launch_bounds__(256) void k_gemm2(
    const float* __restrict__ W2, const float* __restrict__ att_s,
    const float* __restrict__ att_d)
{
    __shared__ float sz[32 * 65];          // padded pitch 65
    __shared__ float sw2[H1C * OUTC];      // 2560 floats
    int tid = threadIdx.x;
    int node0 = blockIdx.x * 32;

    // stage z rows (2048 floats)
    const float* zsrc = g_z + (size_t)node0 * H1C;
#pragma unroll
    for (int i = 0; i < 8; i++) {
        int idx = tid + i * 256;
        sz[(idx >> 6) * 65 + (idx & 63)] = zsrc[idx];
    }
    // stage W2
#pragma unroll
    for (int i = 0; i < 10; i++) sw2[tid + i * 256] = W2[tid + i * 256];
    __syncthreads();

    int ln = tid >> 3;     // 0..31
    int cg = tid & 7;      // cols 5cg..5cg+4
    int c0 = cg * 5;
    const float* zr = sz + ln * 65;
    float acc[5] = {0.f, 0.f, 0.f, 0.f, 0.f};
#pragma unroll 4
    for (int k = 0; k < H1C; k++) {
        float zk = zr[k];
        const float* wr = sw2 + k * OUTC + c0;
#pragma unroll
        for (int c = 0; c < 5; c++) acc[c] += zk * wr[c];
    }
    float ps = 0.f, pd = 0.f;
#pragma unroll
    for (int c = 0; c < 5; c++) {
        ps += acc[c] * __ldg(&att_s[c0 + c]);
        pd += acc[c] * __ldg(&att_d[c0 + c]);
    }
    ps += __shfl_xor_sync(0xffffffffu, ps, 1);
    pd += __shfl_xor_sync(0xffffffffu, pd, 1);
    ps += __shfl_xor_sync(0xffffffffu, ps, 2);
    pd += __shfl_xor_sync(0xffffffffu, pd, 2);
    ps += __shfl_xor_sync(0xffffffffu, ps, 4);
    pd += __shfl_xor_sync(0xffffffffu, pd, 4);

    int n = node0 + ln;
    float w = __expf(leaky(ps + pd));   // self-loop weight
    if (cg == 0) {
        g_as2[n] = ps;
        g_ad2[n] = pd;
        g_den2[n] = w;
    }
#pragma unroll
    for (int c = 0; c < 5; c++) {
        g_h2[(size_t)n * OUTC + c0 + c] = acc[c];
        g_acc2[(size_t)n * OUTC + c0 + c] = w * acc[c];
    }
}

// ---------------- K5: layer-2 edge pass (warp per edge) ----------------------
__global__ __launch_bounds__(256) void k_edge2(
    const int* __restrict__ ei, const float* __restrict__ ew, int e)
{
    int gw = (blockIdx.x * blockDim.x + threadIdx.x) >> 5;
    if (gw >= e) return;
    int lane = threadIdx.x & 31;
    int s = __ldg(&ei[gw]);
    int d = __ldg(&ei[e + gw]);
    float wgt = __ldg(&ew[gw]);

    float w = 0.f;
    if (lane == 0) {
        float t = g_as2[s] + g_ad2[d];
        w = __expf(leaky(t));
        atomicAdd(&g_den2[d], w);
    }
    w = __shfl_sync(0xffffffffu, w, 0) * wgt;
    if (lane < 20) {
        float2 hv = *(const float2*)(g_h2 + (size_t)s * OUTC + lane * 2);
        red2(g_acc2 + (size_t)d * OUTC + lane * 2, w * hv.x, w * hv.y);
    }
}

// ---------------- K6: final output -------------------------------------------
__global__ __launch_bounds__(256) void k_out(float* __restrict__ out,
                                             const float* __restrict__ b2, int n)
{
    int i = blockIdx.x * blockDim.x + threadIdx.x;
    if (i >= n * OUTC) return;
    int node = i / OUTC;
    int j = i - node * OUTC;
    out[i] = g_acc2[i] / (g_den2[node] + 1e-16f) + b2[j];
}

// -----------------------------------------------------------------------------
extern "C" void kernel_launch(void* const* d_in, const int* in_sizes, int n_in,
                              void* d_out, int out_size)
{
    const float* x   = (const float*)d_in[0];
    const int*   ei  = (const int*)d_in[1];
    const float* ew  = (const float*)d_in[2];
    const float* W1  = (const float*)d_in[3];
    const float* as1 = (const float*)d_in[4];
    const float* ad1 = (const float*)d_in[5];
    const float* b1  = (const float*)d_in[6];
    const float* W2  = (const float*)d_in[7];
    const float* as2 = (const float*)d_in[8];
    const float* ad2 = (const float*)d_in[9];
    const float* b2  = (const float*)d_in[10];

    int n = in_sizes[0] / INC;       // 100000
    int e = in_sizes[2];             // 1600000

    k_gemm1<<<n / 16, 256>>>(x, W1, as1, ad1);
    k_edge1<<<(e + 7) / 8, 256>>>(ei, ew, e);
    k_zfin<<<(n * H1C + 255) / 256, 256>>>(b1, n);
    k_gemm2<<<n / 32, 256>>>(W2, as2, ad2);
    k_edge2<<<(e + 7) / 8, 256>>>(ei, ew, e);
    k_out<<<(n * OUTC + 255) / 256, 256>>>((float*)d_out, b2, n);
}

// round 2
// speedup vs baseline: 1.7283x; 1.7283x over previous
#include <cuda_runtime.h>
#include <cstdint>

#define NN 100000
#define EE 1600000
#define INC 128
#define H1C 64      // HEADS*HID
#define HEADS 8
#define OUTC 40

// ---------------- scratch (device globals) -----------------------------------
__device__ float g_h1[NN * H1C];       // layer1 projected features
__device__ float g_as1[NN * HEADS];
__device__ float g_ad1[NN * HEADS];
__device__ float g_acc1[NN * H1C];     // numerator (init w/ self loop)
__device__ float g_den1[NN * HEADS];
__device__ float g_h2[NN * OUTC];
__device__ float g_as2[NN];
__device__ float g_ad2[NN];
__device__ float g_acc2[NN * OUTC];
__device__ float g_den2[NN];

__device__ __forceinline__ void red4(float* addr, float a, float b, float c, float d) {
    asm volatile("red.global.add.v4.f32 [%0], {%1, %2, %3, %4};"
                 :: "l"(addr), "f"(a), "f"(b), "f"(c), "f"(d) : "memory");
}

__device__ __forceinline__ float leaky(float t) {
    return t > 0.f ? t : 0.2f * t;
}

// ---------------- K1: GEMM1 + attention halves + self-loop init --------------
// block 256 thr: tile 64 nodes x 64 cols; thread = 4 nodes x 4 cols
__global__ __launch_bounds__(256) void k_gemm1(
    const float* __restrict__ x, const float* __restrict__ W1,
    const float* __restrict__ att_s, const float* __restrict__ att_d)
{
    __shared__ float sx[64 * 132];   // 64 rows, float pitch 132 (33 float4)
    int tid = threadIdx.x;
    int node0 = blockIdx.x * 64;

    // stage 64 x-rows (2048 float4)
    const float4* x4 = (const float4*)x;
    float4* sx4 = (float4*)sx;
#pragma unroll
    for (int i = 0; i < 8; i++) {
        int idx = tid + i * 256;
        int r = idx >> 5, c = idx & 31;
        int n = node0 + r;
        float4 v = make_float4(0.f, 0.f, 0.f, 0.f);
        if (n < NN) v = x4[(size_t)n * 32 + c];
        sx4[r * 33 + c] = v;
    }
    __syncthreads();

    int cg = tid & 15;        // cols 4cg..4cg+3
    int ng = tid >> 4;        // nodes 4ng..4ng+3
    const float* xr0 = sx + (ng * 4 + 0) * 132;
    const float* xr1 = sx + (ng * 4 + 1) * 132;
    const float* xr2 = sx + (ng * 4 + 2) * 132;
    const float* xr3 = sx + (ng * 4 + 3) * 132;
    const float4* W4 = (const float4*)W1;   // [128][16] float4

    float4 a0 = {0,0,0,0}, a1 = {0,0,0,0}, a2 = {0,0,0,0}, a3 = {0,0,0,0};
#pragma unroll 8
    for (int k = 0; k < INC; k++) {
        float4 w = __ldg(&W4[k * 16 + cg]);
        float v0 = xr0[k], v1 = xr1[k], v2 = xr2[k], v3 = xr3[k];
        a0.x += v0 * w.x; a0.y += v0 * w.y; a0.z += v0 * w.z; a0.w += v0 * w.w;
        a1.x += v1 * w.x; a1.y += v1 * w.y; a1.z += v1 * w.z; a1.w += v1 * w.w;
        a2.x += v2 * w.x; a2.y += v2 * w.y; a2.z += v2 * w.z; a2.w += v2 * w.w;
        a3.x += v3 * w.x; a3.y += v3 * w.y; a3.z += v3 * w.z; a3.w += v3 * w.w;
    }

    float4 as = *(const float4*)(att_s + cg * 4);
    float4 ad = *(const float4*)(att_d + cg * 4);
    float4 acc[4] = {a0, a1, a2, a3};
    float ps[4], pd[4], wv[4];
#pragma unroll
    for (int i = 0; i < 4; i++) {
        ps[i] = acc[i].x * as.x + acc[i].y * as.y + acc[i].z * as.z + acc[i].w * as.w;
        pd[i] = acc[i].x * ad.x + acc[i].y * ad.y + acc[i].z * ad.z + acc[i].w * ad.w;
        ps[i] += __shfl_xor_sync(0xffffffffu, ps[i], 1);   // pair cgs within head
        pd[i] += __shfl_xor_sync(0xffffffffu, pd[i], 1);
        wv[i] = __expf(leaky(ps[i] + pd[i]));              // valid on ALL lanes
    }
    int h = cg >> 1;
#pragma unroll
    for (int i = 0; i < 4; i++) {
        int n = node0 + ng * 4 + i;
        if (n >= NN) continue;
        if ((cg & 1) == 0) {
            g_as1[n * HEADS + h] = ps[i];
            g_ad1[n * HEADS + h] = pd[i];
            g_den1[n * HEADS + h] = wv[i];  // self-loop (ew=1)
        }
        *(float4*)(g_h1 + (size_t)n * H1C + cg * 4) = acc[i];
        float4 ai = make_float4(wv[i] * acc[i].x, wv[i] * acc[i].y,
                                wv[i] * acc[i].z, wv[i] * acc[i].w);
        *(float4*)(g_acc1 + (size_t)n * H1C + cg * 4) = ai;
    }
}

// ---------------- K2: layer-1 edge pass (half-warp per edge, v4 reds) --------
__global__ __launch_bounds__(256) void k_edge1(
    const int* __restrict__ ei, const float* __restrict__ ew, int e)
{
    int t = blockIdx.x * 256 + threadIdx.x;
    int eid = t >> 4;
    if (eid >= e) return;
    int lane = threadIdx.x & 31;
    int hl = lane & 15;

    int s = __ldg(&ei[eid]);
    int d = __ldg(&ei[e + eid]);
    float wgt = __ldg(&ew[eid]);

    float w = 0.f;
    if (hl < 8) {
        float tt = __ldg(&g_as1[s * HEADS + hl]) + __ldg(&g_ad1[d * HEADS + hl]);
        w = __expf(leaky(tt));
        atomicAdd(&g_den1[d * HEADS + hl], w);
    }
    // channel lane hl covers cols 4hl..4hl+3 -> head = hl>>1, w lives on lane (base + hl>>1)
    int src_lane = (lane & 16) | (hl >> 1);
    float wh = __shfl_sync(0xffffffffu, w, src_lane) * wgt;
    float4 hv = *(const float4*)(g_h1 + (size_t)s * H1C + hl * 4);
    red4(g_acc1 + (size_t)d * H1C + hl * 4,
         wh * hv.x, wh * hv.y, wh * hv.z, wh * hv.w);
}

// ---------------- K3: GEMM2 (elu fused in staging) + attention + self loop ---
// block 256 thr: tile 128 nodes x 40 cols; thread = 4 nodes x 5 cols
__global__ __launch_bounds__(256) void k_gemm2(
    const float* __restrict__ W2, const float* __restrict__ att_s,
    const float* __restrict__ att_d, const float* __restrict__ b1)
{
    __shared__ float sz[128 * 68];   // elu(layer1) tile, pitch 68
    __shared__ float sw4[64 * 32];   // W2 cols c0..c0+3 per cg (float4 aligned)
    __shared__ float sw1[64 * 8];    // W2 col c0+4 per cg
    int tid = threadIdx.x;
    int node0 = blockIdx.x * 128;

    // stage z = elu(acc1/den1 + b1) : 128 nodes x 16 float4
    const float4* acc1_4 = (const float4*)g_acc1;
    const float4* b1_4 = (const float4*)b1;
#pragma unroll
    for (int i = 0; i < 8; i++) {
        int idx = tid + i * 256;           // 0..2047
        int r = idx >> 4, c = idx & 15;    // node row, float4 col
        int n = node0 + r;
        float4 v = make_float4(0.f, 0.f, 0.f, 0.f);
        if (n < NN) {
            float4 a = acc1_4[(size_t)n * 16 + c];
            float den = g_den1[n * HEADS + (c >> 1)] + 1e-16f;
            float4 b = b1_4[c];
            float inv = 1.f / den;
            v.x = a.x * inv + b.x; v.y = a.y * inv + b.y;
            v.z = a.z * inv + b.z; v.w = a.w * inv + b.w;
            v.x = v.x > 0.f ? v.x : __expf(v.x) - 1.f;
            v.y = v.y > 0.f ? v.y : __expf(v.y) - 1.f;
            v.z = v.z > 0.f ? v.z : __expf(v.z) - 1.f;
            v.w = v.w > 0.f ? v.w : __expf(v.w) - 1.f;
        }
        *(float4*)(sz + r * 68 + c * 4) = v;
    }
    // stage W2 split into 4-wide + 1 per col-group
#pragma unroll
    for (int i = 0; i < 10; i++) {
        int idx = tid + i * 256;           // 0..2559
        int k = idx / OUTC, r = idx - k * OUTC;
        int cgg = r / 5, j = r - cgg * 5;
        float v = W2[idx];
        if (j < 4) sw4[k * 32 + cgg * 4 + j] = v;
        else       sw1[k * 8 + cgg] = v;
    }
    __syncthreads();

    int cg = tid & 7;      // cols 5cg..5cg+4
    int ng = tid >> 3;     // nodes 4ng..4ng+3
    int c0 = cg * 5;
    const float* zr0 = sz + (ng * 4 + 0) * 68;
    const float* zr1 = sz + (ng * 4 + 1) * 68;
    const float* zr2 = sz + (ng * 4 + 2) * 68;
    const float* zr3 = sz + (ng * 4 + 3) * 68;

    float acc[4][5];
#pragma unroll
    for (int i = 0; i < 4; i++)
#pragma unroll
        for (int c = 0; c < 5; c++) acc[i][c] = 0.f;

#pragma unroll 4
    for (int k = 0; k < H1C; k++) {
        float4 w = *(const float4*)(sw4 + k * 32 + cg * 4);
        float w5 = sw1[k * 8 + cg];
        float z0 = zr0[k], z1 = zr1[k], z2 = zr2[k], z3 = zr3[k];
        acc[0][0] += z0 * w.x; acc[0][1] += z0 * w.y; acc[0][2] += z0 * w.z; acc[0][3] += z0 * w.w; acc[0][4] += z0 * w5;
        acc[1][0] += z1 * w.x; acc[1][1] += z1 * w.y; acc[1][2] += z1 * w.z; acc[1][3] += z1 * w.w; acc[1][4] += z1 * w5;
        acc[2][0] += z2 * w.x; acc[2][1] += z2 * w.y; acc[2][2] += z2 * w.z; acc[2][3] += z2 * w.w; acc[2][4] += z2 * w5;
        acc[3][0] += z3 * w.x; acc[3][1] += z3 * w.y; acc[3][2] += z3 * w.z; acc[3][3] += z3 * w.w; acc[3][4] += z3 * w5;
    }

    float ats[5], atd[5];
#pragma unroll
    for (int c = 0; c < 5; c++) { ats[c] = __ldg(&att_s[c0 + c]); atd[c] = __ldg(&att_d[c0 + c]); }

    float ps[4], pd[4], wv[4];
#pragma unroll
    for (int i = 0; i < 4; i++) {
        float s_ = 0.f, d_ = 0.f;
#pragma unroll
        for (int c = 0; c < 5; c++) { s_ += acc[i][c] * ats[c]; d_ += acc[i][c] * atd[c]; }
        s_ += __shfl_xor_sync(0xffffffffu, s_, 1);
        d_ += __shfl_xor_sync(0xffffffffu, d_, 1);
        s_ += __shfl_xor_sync(0xffffffffu, s_, 2);
        d_ += __shfl_xor_sync(0xffffffffu, d_, 2);
        s_ += __shfl_xor_sync(0xffffffffu, s_, 4);
        d_ += __shfl_xor_sync(0xffffffffu, d_, 4);
        ps[i] = s_; pd[i] = d_;
        wv[i] = __expf(leaky(s_ + d_));   // valid on all lanes
    }

#pragma unroll
    for (int i = 0; i < 4; i++) {
        int n = node0 + ng * 4 + i;
        if (n >= NN) continue;
        if (cg == 0) {
            g_as2[n] = ps[i];
            g_ad2[n] = pd[i];
            g_den2[n] = wv[i];   // self loop
        }
        float* hp = g_h2 + (size_t)n * OUTC + c0;
        float* ap = g_acc2 + (size_t)n * OUTC + c0;
#pragma unroll
        for (int c = 0; c < 5; c++) {
            hp[c] = acc[i][c];
            ap[c] = wv[i] * acc[i][c];
        }
    }
}

// ---------------- K4: layer-2 edge pass (half-warp per edge, v4 reds) --------
__global__ __launch_bounds__(256) void k_edge2(
    const int* __restrict__ ei, const float* __restrict__ ew, int e)
{
    int t = blockIdx.x * 256 + threadIdx.x;
    int eid = t >> 4;
    if (eid >= e) return;
    int lane = threadIdx.x & 31;
    int hl = lane & 15;

    int s = __ldg(&ei[eid]);
    int d = __ldg(&ei[e + eid]);
    float wgt = __ldg(&ew[eid]);

    float w = 0.f;
    if (hl == 0) {
        float tt = __ldg(&g_as2[s]) + __ldg(&g_ad2[d]);
        w = __expf(leaky(tt));
        atomicAdd(&g_den2[d], w);
    }
    w = __shfl_sync(0xffffffffu, w, lane & 16) * wgt;
    if (hl < 10) {
        float4 hv = *(const float4*)(g_h2 + (size_t)s * OUTC + hl * 4);
        red4(g_acc2 + (size_t)d * OUTC + hl * 4,
             w * hv.x, w * hv.y, w * hv.z, w * hv.w);
    }
}

// ---------------- K5: final output -------------------------------------------
__global__ __launch_bounds__(256) void k_out(float* __restrict__ out,
                                             const float* __restrict__ b2, int n)
{
    int i = blockIdx.x * blockDim.x + threadIdx.x;
    if (i >= n * OUTC) return;
    int node = i / OUTC;
    int j = i - node * OUTC;
    out[i] = g_acc2[i] / (g_den2[node] + 1e-16f) + b2[j];
}

// -----------------------------------------------------------------------------
extern "C" void kernel_launch(void* const* d_in, const int* in_sizes, int n_in,
                              void* d_out, int out_size)
{
    const float* x   = (const float*)d_in[0];
    const int*   ei  = (const int*)d_in[1];
    const float* ew  = (const float*)d_in[2];
    const float* W1  = (const float*)d_in[3];
    const float* as1 = (const float*)d_in[4];
    const float* ad1 = (const float*)d_in[5];
    const float* b1  = (const float*)d_in[6];
    const float* W2  = (const float*)d_in[7];
    const float* as2 = (const float*)d_in[8];
    const float* ad2 = (const float*)d_in[9];
    const float* b2  = (const float*)d_in[10];

    int n = in_sizes[0] / INC;       // 100000
    int e = in_sizes[2];             // 1600000

    k_gemm1<<<(n + 63) / 64, 256>>>(x, W1, as1, ad1);
    k_edge1<<<(e * 16 + 255) / 256, 256>>>(ei, ew, e);
    k_gemm2<<<(n + 127) / 128, 256>>>(W2, as2, ad2, b1);
    k_edge2<<<(e * 16 + 255) / 256, 256>>>(ei, ew, e);
    k_out<<<(n * OUTC + 255) / 256, 256>>>((float*)d_out, b2, n);
}

// round 3
// speedup vs baseline: 2.1947x; 1.2699x over previous
#include <cuda_runtime.h>
#include <cstdint>

#define NN 100000
#define EE 1600000
#define INC 128
#define H1C 64      // HEADS*HID
#define HEADS 8
#define OUTC 40
#define SCB 1024

// ---------------- scratch (device globals) -----------------------------------
__device__ float g_h1[NN * H1C];
__device__ float g_as1[NN * HEADS];
__device__ float g_ad1[NN * HEADS];
__device__ float g_z[NN * H1C];        // elu(layer1 out)
__device__ float g_h2[NN * OUTC];
__device__ float g_as2[NN];
__device__ float g_ad2[NN];
// CSR build
__device__ int   g_cnt[NN];
__device__ int   g_off[NN + 1];
__device__ int   g_cur[NN];
__device__ int   g_bsum[128];
__device__ int   g_srcs[EE];
__device__ float g_wgts[EE];

__device__ __forceinline__ float leaky(float t) {
    return t > 0.f ? t : 0.2f * t;
}

// ================= CSR build ==================================================
__global__ __launch_bounds__(256) void k_zero(int n)
{
    int i = blockIdx.x * 256 + threadIdx.x;
    if (i < n) g_cnt[i] = 0;
}

__global__ __launch_bounds__(256) void k_hist(const int* __restrict__ ei, int e)
{
    int i = blockIdx.x * 256 + threadIdx.x;
    if (i < e) atomicAdd(&g_cnt[__ldg(&ei[e + i])], 1);
}

__global__ __launch_bounds__(SCB) void k_scan1(int n)
{
    __shared__ int sred[32];
    int i = blockIdx.x * SCB + threadIdx.x;
    int c = (i < n) ? g_cnt[i] : 0;
#pragma unroll
    for (int o = 16; o; o >>= 1) c += __shfl_down_sync(~0u, c, o);
    if ((threadIdx.x & 31) == 0) sred[threadIdx.x >> 5] = c;
    __syncthreads();
    if (threadIdx.x < 32) {
        int v = sred[threadIdx.x];
#pragma unroll
        for (int o = 16; o; o >>= 1) v += __shfl_down_sync(~0u, v, o);
        if (threadIdx.x == 0) g_bsum[blockIdx.x] = v;
    }
}

__global__ __launch_bounds__(128) void k_scan2(int nb)
{
    __shared__ int s[128];
    int t = threadIdx.x;
    int v = (t < nb) ? g_bsum[t] : 0;
    s[t] = v; __syncthreads();
#pragma unroll
    for (int o = 1; o < 128; o <<= 1) {
        int u = (t >= o) ? s[t - o] : 0;
        __syncthreads();
        s[t] += u;
        __syncthreads();
    }
    if (t < nb) g_bsum[t] = s[t] - v;   // exclusive
}

__global__ __launch_bounds__(SCB) void k_scan3(int n)
{
    __shared__ int s[SCB];
    int t = threadIdx.x;
    int i = blockIdx.x * SCB + t;
    int c = (i < n) ? g_cnt[i] : 0;
    s[t] = c; __syncthreads();
#pragma unroll
    for (int o = 1; o < SCB; o <<= 1) {
        int u = (t >= o) ? s[t - o] : 0;
        __syncthreads();
        s[t] += u;
        __syncthreads();
    }
    int off = g_bsum[blockIdx.x] + s[t] - c;
    if (i < n) {
        g_off[i] = off;
        g_cur[i] = off;
        if (i == n - 1) g_off[n] = off + c;
    }
}

__global__ __launch_bounds__(256) void k_scatter(
    const int* __restrict__ ei, const float* __restrict__ ew, int e)
{
    int i = blockIdx.x * 256 + threadIdx.x;
    if (i >= e) return;
    int s = __ldg(&ei[i]);
    int d = __ldg(&ei[e + i]);
    int p = atomicAdd(&g_cur[d], 1);
    g_srcs[p] = s;
    g_wgts[p] = __ldg(&ew[i]);
}

// ================= K_gemm1: x@W1 + attention halves ===========================
// block 256 thr: tile 64 nodes x 64 cols; thread = 4 nodes x 4 cols
__global__ __launch_bounds__(256) void k_gemm1(
    const float* __restrict__ x, const float* __restrict__ W1,
    const float* __restrict__ att_s, const float* __restrict__ att_d)
{
    __shared__ float sx[64 * 132];
    int tid = threadIdx.x;
    int node0 = blockIdx.x * 64;

    const float4* x4 = (const float4*)x;
    float4* sx4 = (float4*)sx;
#pragma unroll
    for (int i = 0; i < 8; i++) {
        int idx = tid + i * 256;
        int r = idx >> 5, c = idx & 31;
        int n = node0 + r;
        float4 v = make_float4(0.f, 0.f, 0.f, 0.f);
        if (n < NN) v = x4[(size_t)n * 32 + c];
        sx4[r * 33 + c] = v;
    }
    __syncthreads();

    int cg = tid & 15;
    int ng = tid >> 4;
    const float* xr0 = sx + (ng * 4 + 0) * 132;
    const float* xr1 = sx + (ng * 4 + 1) * 132;
    const float* xr2 = sx + (ng * 4 + 2) * 132;
    const float* xr3 = sx + (ng * 4 + 3) * 132;
    const float4* W4 = (const float4*)W1;

    float4 a0 = {0,0,0,0}, a1 = {0,0,0,0}, a2 = {0,0,0,0}, a3 = {0,0,0,0};
#pragma unroll 8
    for (int k = 0; k < INC; k++) {
        float4 w = __ldg(&W4[k * 16 + cg]);
        float v0 = xr0[k], v1 = xr1[k], v2 = xr2[k], v3 = xr3[k];
        a0.x += v0 * w.x; a0.y += v0 * w.y; a0.z += v0 * w.z; a0.w += v0 * w.w;
        a1.x += v1 * w.x; a1.y += v1 * w.y; a1.z += v1 * w.z; a1.w += v1 * w.w;
        a2.x += v2 * w.x; a2.y += v2 * w.y; a2.z += v2 * w.z; a2.w += v2 * w.w;
        a3.x += v3 * w.x; a3.y += v3 * w.y; a3.z += v3 * w.z; a3.w += v3 * w.w;
    }

    float4 as = *(const float4*)(att_s + cg * 4);
    float4 ad = *(const float4*)(att_d + cg * 4);
    float4 acc[4] = {a0, a1, a2, a3};
    int h = cg >> 1;
#pragma unroll
    for (int i = 0; i < 4; i++) {
        float ps = acc[i].x * as.x + acc[i].y * as.y + acc[i].z * as.z + acc[i].w * as.w;
        float pd = acc[i].x * ad.x + acc[i].y * ad.y + acc[i].z * ad.z + acc[i].w * ad.w;
        ps += __shfl_xor_sync(0xffffffffu, ps, 1);
        pd += __shfl_xor_sync(0xffffffffu, pd, 1);
        int n = node0 + ng * 4 + i;
        if (n < NN) {
            if ((cg & 1) == 0) {
                g_as1[n * HEADS + h] = ps;
                g_ad1[n * HEADS + h] = pd;
            }
            *(float4*)(g_h1 + (size_t)n * H1C + cg * 4) = acc[i];
        }
    }
}

// ================= K_agg1: warp-per-node gather aggregation (layer 1) ========
// output z = elu(softmax-agg + b1) fused
__global__ __launch_bounds__(256) void k_agg1(const float* __restrict__ b1, int n)
{
    int d = blockIdx.x * 8 + (threadIdx.x >> 5);
    if (d >= n) return;
    int lane = threadIdx.x & 31;
    int h = lane & 7;
    int hc = lane >> 2;   // head of channels 2*lane, 2*lane+1; den/e live on lane hc

    float adh = __ldg(&g_ad1[d * HEADS + h]);
    float ash = __ldg(&g_as1[d * HEADS + h]);

    // self-loop (ew = 1)
    float e0 = __expf(leaky(ash + adh));
    float den = e0;
    float2 hv = *(const float2*)(g_h1 + (size_t)d * H1C + lane * 2);
    float w0 = __shfl_sync(0xffffffffu, e0, hc);
    float2 acc = make_float2(w0 * hv.x, w0 * hv.y);

    int beg = g_off[d], end = g_off[d + 1];
    for (int base = beg; base < end; base += 32) {
        int idx = base + lane;
        int src = d; float wgt = 0.f, va = 0.f;
        if (idx < end) {
            src = __ldg(&g_srcs[idx]);
            wgt = __ldg(&g_wgts[idx]);
            va = 1.f;
        }
        int m4 = (min(32, end - base) + 3) & ~3;
        for (int j = 0; j < m4; j += 4) {
#pragma unroll
            for (int jj = 0; jj < 4; jj++) {
                int s = __shfl_sync(0xffffffffu, src, j + jj);
                float wj = __shfl_sync(0xffffffffu, wgt, j + jj);
                float vj = __shfl_sync(0xffffffffu, va, j + jj);
                float e = __expf(leaky(__ldg(&g_as1[s * HEADS + h]) + adh)) * vj;
                den += e;
                float w = __shfl_sync(0xffffffffu, e, hc) * wj;
                float2 sv = *(const float2*)(g_h1 + (size_t)s * H1C + lane * 2);
                acc.x += w * sv.x;
                acc.y += w * sv.y;
            }
        }
    }
    float dench = __shfl_sync(0xffffffffu, den, hc);
    float inv = 1.f / (dench + 1e-16f);
    float2 bb = *(const float2*)(b1 + lane * 2);
    float zx = acc.x * inv + bb.x;
    float zy = acc.y * inv + bb.y;
    zx = zx > 0.f ? zx : __expf(zx) - 1.f;
    zy = zy > 0.f ? zy : __expf(zy) - 1.f;
    *(float2*)(g_z + (size_t)d * H1C + lane * 2) = make_float2(zx, zy);
}

// ================= K_gemm2: z@W2 + attention ==================================
// block 256 = 128 nodes x 8 col-groups (5 cols); thread = 4 nodes x 5 cols
__global__ __launch_bounds__(256) void k_gemm2(
    const float* __restrict__ W2, const float* __restrict__ att_s,
    const float* __restrict__ att_d)
{
    __shared__ float sz[128 * 68];
    __shared__ float sw4[64 * 32];
    __shared__ float sw1[64 * 8];
    int tid = threadIdx.x;
    int node0 = blockIdx.x * 128;

    const float4* z4 = (const float4*)g_z;
#pragma unroll
    for (int i = 0; i < 8; i++) {
        int idx = tid + i * 256;
        int r = idx >> 4, c = idx & 15;
        int n = node0 + r;
        float4 v = make_float4(0.f, 0.f, 0.f, 0.f);
        if (n < NN) v = z4[(size_t)n * 16 + c];
        *(float4*)(sz + r * 68 + c * 4) = v;
    }
#pragma unroll
    for (int i = 0; i < 10; i++) {
        int idx = tid + i * 256;
        int k = idx / OUTC, r = idx - k * OUTC;
        int cgg = r / 5, j = r - cgg * 5;
        float v = W2[idx];
        if (j < 4) sw4[k * 32 + cgg * 4 + j] = v;
        else       sw1[k * 8 + cgg] = v;
    }
    __syncthreads();

    int cg = tid & 7;
    int ng = tid >> 3;
    int c0 = cg * 5;
    const float* zr0 = sz + (ng * 4 + 0) * 68;
    const float* zr1 = sz + (ng * 4 + 1) * 68;
    const float* zr2 = sz + (ng * 4 + 2) * 68;
    const float* zr3 = sz + (ng * 4 + 3) * 68;

    float acc[4][5];
#pragma unroll
    for (int i = 0; i < 4; i++)
#pragma unroll
        for (int c = 0; c < 5; c++) acc[i][c] = 0.f;

#pragma unroll 4
    for (int k = 0; k < H1C; k++) {
        float4 w = *(const float4*)(sw4 + k * 32 + cg * 4);
        float w5 = sw1[k * 8 + cg];
        float z0 = zr0[k], z1 = zr1[k], z2 = zr2[k], z3 = zr3[k];
        acc[0][0] += z0 * w.x; acc[0][1] += z0 * w.y; acc[0][2] += z0 * w.z; acc[0][3] += z0 * w.w; acc[0][4] += z0 * w5;
        acc[1][0] += z1 * w.x; acc[1][1] += z1 * w.y; acc[1][2] += z1 * w.z; acc[1][3] += z1 * w.w; acc[1][4] += z1 * w5;
        acc[2][0] += z2 * w.x; acc[2][1] += z2 * w.y; acc[2][2] += z2 * w.z; acc[2][3] += z2 * w.w; acc[2][4] += z2 * w5;
        acc[3][0] += z3 * w.x; acc[3][1] += z3 * w.y; acc[3][2] += z3 * w.z; acc[3][3] += z3 * w.w; acc[3][4] += z3 * w5;
    }

    float ats[5], atd[5];
#pragma unroll
    for (int c = 0; c < 5; c++) { ats[c] = __ldg(&att_s[c0 + c]); atd[c] = __ldg(&att_d[c0 + c]); }

#pragma unroll
    for (int i = 0; i < 4; i++) {
        float s_ = 0.f, d_ = 0.f;
#pragma unroll
        for (int c = 0; c < 5; c++) { s_ += acc[i][c] * ats[c]; d_ += acc[i][c] * atd[c]; }
        s_ += __shfl_xor_sync(0xffffffffu, s_, 1);
        d_ += __shfl_xor_sync(0xffffffffu, d_, 1);
        s_ += __shfl_xor_sync(0xffffffffu, s_, 2);
        d_ += __shfl_xor_sync(0xffffffffu, d_, 2);
        s_ += __shfl_xor_sync(0xffffffffu, s_, 4);
        d_ += __shfl_xor_sync(0xffffffffu, d_, 4);
        int nd = node0 + ng * 4 + i;
        if (nd < NN) {
            if (cg == 0) {
                g_as2[nd] = s_;
                g_ad2[nd] = d_;
            }
            float* hp = g_h2 + (size_t)nd * OUTC + c0;
#pragma unroll
            for (int c = 0; c < 5; c++) hp[c] = acc[i][c];
        }
    }
}

// ================= K_agg2: warp-per-node aggregation (layer 2) + output ======
__global__ __launch_bounds__(256) void k_agg2(
    float* __restrict__ out, const float* __restrict__ b2, int n)
{
    int d = blockIdx.x * 8 + (threadIdx.x >> 5);
    if (d >= n) return;
    int lane = threadIdx.x & 31;

    float add = __ldg(&g_ad2[d]);
    float asd = __ldg(&g_as2[d]);

    float e0 = __expf(leaky(asd + add));   // self loop
    float den = e0;
    float2 acc = make_float2(0.f, 0.f);
    if (lane < 20) {
        float2 hv = *(const float2*)(g_h2 + (size_t)d * OUTC + lane * 2);
        acc.x = e0 * hv.x;
        acc.y = e0 * hv.y;
    }

    int beg = g_off[d], end = g_off[d + 1];
    for (int base = beg; base < end; base += 32) {
        int idx = base + lane;
        int src = d; float wgt = 0.f, va = 0.f;
        if (idx < end) {
            src = __ldg(&g_srcs[idx]);
            wgt = __ldg(&g_wgts[idx]);
            va = 1.f;
        }
        int m4 = (min(32, end - base) + 3) & ~3;
        for (int j = 0; j < m4; j += 4) {
#pragma unroll
            for (int jj = 0; jj < 4; jj++) {
                int s = __shfl_sync(0xffffffffu, src, j + jj);
                float wj = __shfl_sync(0xffffffffu, wgt, j + jj);
                float vj = __shfl_sync(0xffffffffu, va, j + jj);
                float e = __expf(leaky(__ldg(&g_as2[s]) + add)) * vj;
                den += e;
                float w = e * wj;
                if (lane < 20) {
                    float2 sv = *(const float2*)(g_h2 + (size_t)s * OUTC + lane * 2);
                    acc.x += w * sv.x;
                    acc.y += w * sv.y;
                }
            }
        }
    }
    float inv = 1.f / (den + 1e-16f);
    if (lane < 20) {
        float2 bb = *(const float2*)(b2 + lane * 2);
        float2 r = make_float2(acc.x * inv + bb.x, acc.y * inv + bb.y);
        *(float2*)(out + (size_t)d * OUTC + lane * 2) = r;
    }
}

// -----------------------------------------------------------------------------
extern "C" void kernel_launch(void* const* d_in, const int* in_sizes, int n_in,
                              void* d_out, int out_size)
{
    const float* x   = (const float*)d_in[0];
    const int*   ei  = (const int*)d_in[1];
    const float* ew  = (const float*)d_in[2];
    const float* W1  = (const float*)d_in[3];
    const float* as1 = (const float*)d_in[4];
    const float* ad1 = (const float*)d_in[5];
    const float* b1  = (const float*)d_in[6];
    const float* W2  = (const float*)d_in[7];
    const float* as2 = (const float*)d_in[8];
    const float* ad2 = (const float*)d_in[9];
    const float* b2  = (const float*)d_in[10];

    int n = in_sizes[0] / INC;       // 100000
    int e = in_sizes[2];             // 1600000
    int nb = (n + SCB - 1) / SCB;    // 98

    // CSR build
    k_zero<<<(n + 255) / 256, 256>>>(n);
    k_hist<<<(e + 255) / 256, 256>>>(ei, e);
    k_scan1<<<nb, SCB>>>(n);
    k_scan2<<<1, 128>>>(nb);
    k_scan3<<<nb, SCB>>>(n);
    k_scatter<<<(e + 255) / 256, 256>>>(ei, ew, e);

    // layer 1
    k_gemm1<<<(n + 63) / 64, 256>>>(x, W1, as1, ad1);
    k_agg1<<<(n + 7) / 8, 256>>>(b1, n);

    // layer 2
    k_gemm2<<<(n + 127) / 128, 256>>>(W2, as2, ad2);
    k_agg2<<<(n + 7) / 8, 256>>>((float*)d_out, b2, n);
}